// round 1
// baseline (speedup 1.0000x reference)
#include <cuda_runtime.h>
#include <math.h>

#define Bb 32
#define Nn 200
#define Ss 192
#define Fin 8
#define Hh 64
#define Pp 48
#define FNn 4
#define Kk 10
#define NBb 3
#define BN (Bb*Nn)
#define SH (Ss*Hh)

// scratch buffers (allocation-free rule: __device__ globals)
__device__ float g_X [BN*SH];     // [bn][s][h]
__device__ float g_XW[BN*SH];
__device__ float g_XF[BN*Pp*Hh];
__device__ float g_LA[Nn*Nn];
__device__ float g_LB[Nn*Nn];
__device__ float g_A [Nn*Nn];
__device__ float g_D [Nn];

// ---------------- kernel 1: instance norm (over S, per feature) + proj + node_emb ----
__global__ __launch_bounds__(256) void k_innorm_proj(
    const float* __restrict__ x, const float* __restrict__ in_w, const float* __restrict__ in_b,
    const float* __restrict__ pw, const float* __restrict__ pb, const float* __restrict__ emb)
{
    __shared__ float xs[Ss*Fin];
    __shared__ float pws[Fin*Hh];
    __shared__ float mu[Fin], ri[Fin];
    int bn = blockIdx.x;
    int tid = threadIdx.x;
    const float* xin = x + (size_t)bn*Ss*Fin;
    for (int i = tid; i < Ss*Fin; i += 256) xs[i] = xin[i];
    for (int i = tid; i < Fin*Hh; i += 256) pws[i] = pw[i];
    __syncthreads();
    if (tid < Fin) {
        float s = 0.f, q = 0.f;
        for (int t = 0; t < Ss; t++) { float v = xs[t*Fin+tid]; s += v; q += v*v; }
        float m = s * (1.f/Ss);
        float var = q * (1.f/Ss) - m*m;
        mu[tid] = m; ri[tid] = rsqrtf(var + 1e-5f);
    }
    __syncthreads();
    for (int i = tid; i < Ss*Fin; i += 256) {
        int f = i & (Fin-1);
        xs[i] = (xs[i]-mu[f])*ri[f]*in_w[f] + in_b[f];
    }
    __syncthreads();
    int h = tid & 63, sb = tid >> 6;
    int n = bn % Nn;
    float bias = pb[h] + emb[n*Hh + h];
    float* xo = g_X + (size_t)bn*SH;
    for (int s = sb; s < Ss; s += 4) {
        float acc = bias;
        #pragma unroll
        for (int f = 0; f < Fin; f++) acc += xs[s*Fin+f]*pws[f*Hh+h];
        xo[s*Hh+h] = acc;
    }
}

// ---------------- kernel 2: learned adjacency + combine + GCN normalization (1 block)
__global__ __launch_bounds__(256) void k_adj(
    const float* __restrict__ adj, const float* __restrict__ emb, const float* __restrict__ ga)
{
    int tid = threadIdx.x;
    // la = relu(E E^T)
    for (int e = tid; e < Nn*Nn; e += 256) {
        int i = e / Nn, j = e % Nn;
        float acc = 0.f;
        for (int k = 0; k < Hh; k++) acc += emb[i*Hh+k]*emb[j*Hh+k];
        float v = fmaxf(acc, 0.f);
        g_LA[e] = v; g_LB[e] = v;
    }
    __syncthreads();
    float alpha = ga[0];
    if (tid < Nn) {
        int r = tid;
        const float* la = g_LA + r*Nn;
        float* lb = g_LB + r*Nn;
        int   idxs[Kk];
        float vals[Kk];
        for (int k = 0; k < Kk; k++) {
            float bv = -1e30f; int bi = 0;
            for (int j = 0; j < Nn; j++) { float v = lb[j]; if (v > bv) { bv = v; bi = j; } }
            idxs[k] = bi; vals[k] = la[bi]; lb[bi] = -1e30f;
        }
        // softmax of (la*mask) over all 200 columns (masked-out entries contribute exp(0))
        float mx = 0.f;
        for (int k = 0; k < Kk; k++) mx = fmaxf(mx, vals[k]);
        float base = __expf(0.f - mx);  // use expf for accuracy
        base = expf(0.f - mx);
        float ev[Kk]; float cs = 0.f;
        for (int k = 0; k < Kk; k++) { ev[k] = expf(vals[k]-mx); cs += ev[k]; }
        float inv = 1.f / ((float)(Nn-Kk)*base + cs);
        float* arow = g_A + r*Nn;
        float bsm = base*inv;
        for (int j = 0; j < Nn; j++) arow[j] = bsm;
        for (int k = 0; k < Kk; k++) arow[idxs[k]] = ev[k]*inv;
        // combined + diag=1 + rowsum
        float rs = 0.f;
        for (int j = 0; j < Nn; j++) {
            float c = alpha*adj[r*Nn+j] + (1.f-alpha)*arow[j];
            if (j == r) c = 1.f;
            arow[j] = c; rs += c;
        }
        g_D[r] = rsqrtf(fmaxf(rs, 1.f));
    }
    __syncthreads();
    for (int e = tid; e < Nn*Nn; e += 256) {
        int i = e / Nn, j = e % Nn;
        g_A[e] *= g_D[i]*g_D[j];
    }
}

// ---------------- kernel 3: temporal MLP y = W_t x + b, x += gelu(y), in place ------
__global__ __launch_bounds__(256) void k_temporal(
    const float* __restrict__ W, const float* __restrict__ tb)
{
    __shared__ float xs[SH];          // 48KB
    int bn = blockIdx.x;
    int tid = threadIdx.x;
    float* xg = g_X + (size_t)bn*SH;
    for (int i = tid; i < SH; i += 256) xs[i] = xg[i];
    __syncthreads();
    int h = tid & 63, g = tid >> 6;
    for (int t0 = g*48; t0 < g*48 + 48; t0 += 8) {
        float acc[8] = {0,0,0,0,0,0,0,0};
        for (int s = 0; s < Ss; s++) {
            float xv = xs[s*Hh+h];
            #pragma unroll
            for (int k = 0; k < 8; k++) acc[k] += W[(t0+k)*Ss+s]*xv;
        }
        #pragma unroll
        for (int k = 0; k < 8; k++) {
            int t = t0 + k;
            float y = acc[k] + tb[t];
            float gl = 0.5f*y*(1.f + erff(y*0.70710678118654752f));
            xg[t*Hh+h] = xs[t*Hh+h] + gl;
        }
    }
}

// ---------------- kernel 4: XW = X @ gcn_W  (H x H) -------------------------------
__global__ __launch_bounds__(256) void k_gcnw(const float* __restrict__ W)
{
    __shared__ float xs[SH];          // 48KB
    int bn = blockIdx.x;
    int tid = threadIdx.x;
    const float* xg = g_X  + (size_t)bn*SH;
    float*       xo = g_XW + (size_t)bn*SH;
    for (int i = tid; i < SH; i += 256) xs[i] = xg[i];
    int h = tid & 63, g = tid >> 6;
    float wr[Hh];
    #pragma unroll
    for (int k = 0; k < Hh; k++) wr[k] = W[k*Hh+h];
    __syncthreads();
    for (int s = g; s < Ss; s += 4) {
        float acc = 0.f;
        #pragma unroll
        for (int k = 0; k < Hh; k++) acc += xs[s*Hh+k]*wr[k];
        xo[s*Hh+h] = acc;
    }
}

// ---------------- kernel 5: g = A @ XW + gcn_b ; X = LayerNorm(X+g) fused ----------
#define MT 40
__global__ __launch_bounds__(64) void k_mixln(
    const float* __restrict__ gb, const float* __restrict__ lw, const float* __restrict__ lb)
{
    __shared__ float As[MT*Nn];       // 32KB
    __shared__ float red[2][4];
    int b  = blockIdx.z;
    int m0 = blockIdx.y*MT;
    int s0 = blockIdx.x*2;
    int tid = threadIdx.x;
    int h = tid;
    for (int i = tid; i < MT*Nn; i += 64) {
        int mm = i / Nn, nn = i % Nn;
        As[i] = g_A[(m0+mm)*Nn + nn];
    }
    __syncthreads();
    float acc0[MT], acc1[MT];
    #pragma unroll
    for (int m = 0; m < MT; m++) { acc0[m] = 0.f; acc1[m] = 0.f; }
    const float* xw = g_XW + (size_t)b*Nn*SH + (size_t)s0*Hh + h;
    for (int n = 0; n < Nn; n++) {
        float v0 = xw[(size_t)n*SH];
        float v1 = xw[(size_t)n*SH + Hh];
        #pragma unroll
        for (int m = 0; m < MT; m++) {
            float a = As[m*Nn+n];
            acc0[m] += a*v0;
            acc1[m] += a*v1;
        }
    }
    int lane = tid & 31, w = tid >> 5;
    float gbh = gb[h], lwh = lw[h], lbh = lb[h];
    for (int m = 0; m < MT; m++) {
        size_t xi = ((size_t)b*Nn + m0 + m)*SH + (size_t)s0*Hh + h;
        float v0 = g_X[xi]      + acc0[m] + gbh;
        float v1 = g_X[xi + Hh] + acc1[m] + gbh;
        float s0v = v0, q0 = v0*v0, s1v = v1, q1 = v1*v1;
        #pragma unroll
        for (int o = 16; o > 0; o >>= 1) {
            s0v += __shfl_down_sync(0xffffffffu, s0v, o);
            q0  += __shfl_down_sync(0xffffffffu, q0,  o);
            s1v += __shfl_down_sync(0xffffffffu, s1v, o);
            q1  += __shfl_down_sync(0xffffffffu, q1,  o);
        }
        if (lane == 0) { red[w][0]=s0v; red[w][1]=q0; red[w][2]=s1v; red[w][3]=q1; }
        __syncthreads();
        float S0 = red[0][0]+red[1][0], Q0 = red[0][1]+red[1][1];
        float S1 = red[0][2]+red[1][2], Q1 = red[0][3]+red[1][3];
        __syncthreads();
        float mu0 = S0*(1.f/Hh), var0 = Q0*(1.f/Hh) - mu0*mu0;
        float mu1 = S1*(1.f/Hh), var1 = Q1*(1.f/Hh) - mu1*mu1;
        g_X[xi]      = (v0-mu0)*rsqrtf(var0+1e-5f)*lwh + lbh;
        g_X[xi + Hh] = (v1-mu1)*rsqrtf(var1+1e-5f)*lwh + lbh;
    }
}

// ---------------- kernel 6: future projection -------------------------------------
__global__ __launch_bounds__(256) void k_futr(
    const float* __restrict__ xf, const float* __restrict__ fw, const float* __restrict__ fb)
{
    int idx = blockIdx.x*blockDim.x + threadIdx.x;
    const int tot = BN*Pp*Hh;
    if (idx >= tot) return;
    int h = idx & 63;
    int p = (idx >> 6) % Pp;
    int bn = idx / (Pp*Hh);
    const float* xr = xf + ((size_t)bn*Pp + p)*FNn;
    float acc = fb[h];
    #pragma unroll
    for (int f = 0; f < FNn; f++) acc += xr[f]*fw[f*Hh+h];
    g_XF[idx] = acc;
}

// ---------------- kernel 7: head GEMM  out = [X | XF] @ head_W + head_b ------------
__global__ __launch_bounds__(256) void k_head(
    const float* __restrict__ hw, const float* __restrict__ hb, float* __restrict__ out)
{
    __shared__ float Wt[64][48];      // 12KB
    __shared__ float Ft[16][64];      // 4KB
    const int KH = SH;                // 12288 history part
    const int KT = SH + Pp*Hh;        // 15360 total
    int m0 = blockIdx.x*16;
    int tid = threadIdx.x;
    int pcol = tid & 15, mrow = tid >> 4;
    float a0 = 0.f, a1 = 0.f, a2 = 0.f;
    for (int k0 = 0; k0 < KT; k0 += 64) {
        for (int i = tid; i < 64*48; i += 256) {
            int kl = i / 48, p = i % 48;
            Wt[kl][p] = hw[(size_t)(k0+kl)*48 + p];
        }
        for (int i = tid; i < 16*64; i += 256) {
            int ml = i >> 6, kl = i & 63;
            int m = m0 + ml;
            float v;
            if (k0 < KH) v = g_X[(size_t)m*KH + k0 + kl];
            else         v = g_XF[(size_t)m*(Pp*Hh) + (k0 - KH) + kl];
            Ft[ml][kl] = v;
        }
        __syncthreads();
        #pragma unroll 16
        for (int kk = 0; kk < 64; kk++) {
            float fv = Ft[mrow][kk];
            a0 += fv*Wt[kk][pcol];
            a1 += fv*Wt[kk][pcol+16];
            a2 += fv*Wt[kk][pcol+32];
        }
        __syncthreads();
    }
    int m = m0 + mrow;
    out[(size_t)m*Pp + pcol]      = a0 + hb[pcol];
    out[(size_t)m*Pp + pcol + 16] = a1 + hb[pcol+16];
    out[(size_t)m*Pp + pcol + 32] = a2 + hb[pcol+32];
}

// ---------------- launcher ---------------------------------------------------------
extern "C" void kernel_launch(void* const* d_in, const int* in_sizes, int n_in,
                              void* d_out, int out_size)
{
    const float* x        = (const float*)d_in[0];
    const float* x_future = (const float*)d_in[1];
    const float* adj      = (const float*)d_in[2];
    const float* node_emb = (const float*)d_in[3];
    const float* galpha   = (const float*)d_in[4];
    const float* in_w     = (const float*)d_in[5];
    const float* in_b     = (const float*)d_in[6];
    const float* proj_W   = (const float*)d_in[7];
    const float* proj_b   = (const float*)d_in[8];
    const float* temp_W   = (const float*)d_in[9];
    const float* temp_b   = (const float*)d_in[10];
    const float* gcn_W    = (const float*)d_in[11];
    const float* gcn_b    = (const float*)d_in[12];
    const float* ln_w     = (const float*)d_in[13];
    const float* ln_b     = (const float*)d_in[14];
    const float* futr_W   = (const float*)d_in[15];
    const float* futr_b   = (const float*)d_in[16];
    const float* head_W   = (const float*)d_in[17];
    const float* head_b   = (const float*)d_in[18];
    float* out = (float*)d_out;

    k_innorm_proj<<<BN, 256>>>(x, in_w, in_b, proj_W, proj_b, node_emb);
    k_adj<<<1, 256>>>(adj, node_emb, galpha);
    for (int i = 0; i < NBb; i++) {
        k_temporal<<<BN, 256>>>(temp_W + (size_t)i*Ss*Ss, temp_b + (size_t)i*Ss);
        k_gcnw<<<BN, 256>>>(gcn_W + (size_t)i*Hh*Hh);
        k_mixln<<<dim3(Ss/2, Nn/MT, Bb), 64>>>(gcn_b + (size_t)i*Hh,
                                               ln_w + (size_t)i*Hh, ln_b + (size_t)i*Hh);
    }
    {
        const int tot = BN*Pp*Hh;
        k_futr<<<(tot + 255)/256, 256>>>(x_future, futr_W, futr_b);
    }
    k_head<<<BN/16, 256>>>(head_W, head_b, out);
}

// round 2
// speedup vs baseline: 1.3080x; 1.3080x over previous
#include <cuda_runtime.h>
#include <math.h>

#define Bb 32
#define Nn 200
#define Ss 192
#define Fin 8
#define Hh 64
#define Pp 48
#define FNn 4
#define Kk 10
#define NBb 3
#define BN (Bb*Nn)
#define SH (Ss*Hh)

// scratch buffers (allocation-free rule: __device__ globals)
__device__ float g_X [BN*SH];     // [bn][s][h]
__device__ float g_XW[BN*SH];
__device__ float g_XF[BN*Pp*Hh];
__device__ float g_LA[Nn*Nn];
__device__ float g_LB[Nn*Nn];
__device__ float g_A [Nn*Nn];
__device__ float g_D [Nn];
__device__ float g_WT[Ss*Ss];     // transposed temporal weight [s][t]

__device__ __forceinline__ float gelu_exact(float y) {
    return 0.5f*y*(1.f + erff(y*0.70710678118654752f));
}

// ---------------- kernel 1: instance norm (over S, per feature) + proj + node_emb ----
__global__ __launch_bounds__(256) void k_innorm_proj(
    const float* __restrict__ x, const float* __restrict__ in_w, const float* __restrict__ in_b,
    const float* __restrict__ pw, const float* __restrict__ pb, const float* __restrict__ emb)
{
    __shared__ float xs[Ss*Fin];
    __shared__ float pws[Fin*Hh];
    __shared__ float mu[Fin], ri[Fin];
    int bn = blockIdx.x;
    int tid = threadIdx.x;
    const float* xin = x + (size_t)bn*Ss*Fin;
    for (int i = tid; i < Ss*Fin; i += 256) xs[i] = xin[i];
    for (int i = tid; i < Fin*Hh; i += 256) pws[i] = pw[i];
    __syncthreads();
    if (tid < Fin) {
        float s = 0.f, q = 0.f;
        for (int t = 0; t < Ss; t++) { float v = xs[t*Fin+tid]; s += v; q += v*v; }
        float m = s * (1.f/Ss);
        float var = q * (1.f/Ss) - m*m;
        mu[tid] = m; ri[tid] = rsqrtf(var + 1e-5f);
    }
    __syncthreads();
    for (int i = tid; i < Ss*Fin; i += 256) {
        int f = i & (Fin-1);
        xs[i] = (xs[i]-mu[f])*ri[f]*in_w[f] + in_b[f];
    }
    __syncthreads();
    int h = tid & 63, sb = tid >> 6;
    int n = bn % Nn;
    float bias = pb[h] + emb[n*Hh + h];
    float* xo = g_X + (size_t)bn*SH;
    for (int s = sb; s < Ss; s += 4) {
        float acc = bias;
        #pragma unroll
        for (int f = 0; f < Fin; f++) acc += xs[s*Fin+f]*pws[f*Hh+h];
        xo[s*Hh+h] = acc;
    }
}

// ---------------- kernel 2: learned adjacency + combine + GCN normalization (1 block)
__global__ __launch_bounds__(256) void k_adj(
    const float* __restrict__ adj, const float* __restrict__ emb, const float* __restrict__ ga)
{
    int tid = threadIdx.x;
    for (int e = tid; e < Nn*Nn; e += 256) {
        int i = e / Nn, j = e % Nn;
        float acc = 0.f;
        for (int k = 0; k < Hh; k++) acc += emb[i*Hh+k]*emb[j*Hh+k];
        float v = fmaxf(acc, 0.f);
        g_LA[e] = v; g_LB[e] = v;
    }
    __syncthreads();
    float alpha = ga[0];
    if (tid < Nn) {
        int r = tid;
        const float* la = g_LA + r*Nn;
        float* lb = g_LB + r*Nn;
        int   idxs[Kk];
        float vals[Kk];
        for (int k = 0; k < Kk; k++) {
            float bv = -1e30f; int bi = 0;
            for (int j = 0; j < Nn; j++) { float v = lb[j]; if (v > bv) { bv = v; bi = j; } }
            idxs[k] = bi; vals[k] = la[bi]; lb[bi] = -1e30f;
        }
        float mx = 0.f;
        for (int k = 0; k < Kk; k++) mx = fmaxf(mx, vals[k]);
        float base = expf(0.f - mx);
        float ev[Kk]; float cs = 0.f;
        for (int k = 0; k < Kk; k++) { ev[k] = expf(vals[k]-mx); cs += ev[k]; }
        float inv = 1.f / ((float)(Nn-Kk)*base + cs);
        float* arow = g_A + r*Nn;
        float bsm = base*inv;
        for (int j = 0; j < Nn; j++) arow[j] = bsm;
        for (int k = 0; k < Kk; k++) arow[idxs[k]] = ev[k]*inv;
        float rs = 0.f;
        for (int j = 0; j < Nn; j++) {
            float c = alpha*adj[r*Nn+j] + (1.f-alpha)*arow[j];
            if (j == r) c = 1.f;
            arow[j] = c; rs += c;
        }
        g_D[r] = rsqrtf(fmaxf(rs, 1.f));
    }
    __syncthreads();
    for (int e = tid; e < Nn*Nn; e += 256) {
        int i = e / Nn, j = e % Nn;
        g_A[e] *= g_D[i]*g_D[j];
    }
}

// ---------------- kernel: transpose temporal weight (W[t][s] -> WT[s][t]) ----------
__global__ void k_wt(const float* __restrict__ W)
{
    __shared__ float t[32][33];
    int bx = blockIdx.x*32, by = blockIdx.y*32;
    t[threadIdx.y][threadIdx.x] = W[(by+threadIdx.y)*Ss + bx + threadIdx.x];
    __syncthreads();
    g_WT[(bx+threadIdx.y)*Ss + by + threadIdx.x] = t[threadIdx.x][threadIdx.y];
}

// ---------------- fused: temporal MLP (x += gelu(Wx+b)) + XW = x @ gcn_W ----------
// block handles 2 (b,n) tiles. 256 threads: hp = tid&31 (h pair), tg = tid>>5 (8 t-groups of 24)
__global__ __launch_bounds__(256, 2) void k_tempgcn(
    const float* __restrict__ tb, const float* __restrict__ Wg)
{
    extern __shared__ float xs[];     // 2 * SH floats = 96KB
    int tid = threadIdx.x;
    int bn0 = blockIdx.x*2;
    float* xg0 = g_X + (size_t)bn0*SH;
    float* xg1 = xg0 + SH;
    for (int i = tid; i < SH; i += 256) { xs[i] = xg0[i]; xs[SH+i] = xg1[i]; }
    __syncthreads();

    int hp = tid & 31;                // h = 2*hp
    int tg = tid >> 5;                // 0..7
    int tbase = tg*24;

    float2 acc0[24], acc1[24];
    #pragma unroll
    for (int k = 0; k < 24; k++) { acc0[k] = make_float2(0.f,0.f); acc1[k] = make_float2(0.f,0.f); }

    const float* wtbase = g_WT + tbase;
    for (int s = 0; s < Ss; s++) {
        float2 xa = *(const float2*)(xs + s*Hh + 2*hp);
        float2 xb = *(const float2*)(xs + SH + s*Hh + 2*hp);
        const float4* wp = (const float4*)(wtbase + s*Ss);
        #pragma unroll
        for (int c = 0; c < 6; c++) {
            float4 w = wp[c];
            int k = c*4;
            acc0[k+0].x += w.x*xa.x; acc0[k+0].y += w.x*xa.y;
            acc1[k+0].x += w.x*xb.x; acc1[k+0].y += w.x*xb.y;
            acc0[k+1].x += w.y*xa.x; acc0[k+1].y += w.y*xa.y;
            acc1[k+1].x += w.y*xb.x; acc1[k+1].y += w.y*xb.y;
            acc0[k+2].x += w.z*xa.x; acc0[k+2].y += w.z*xa.y;
            acc1[k+2].x += w.z*xb.x; acc1[k+2].y += w.z*xb.y;
            acc0[k+3].x += w.w*xa.x; acc0[k+3].y += w.w*xa.y;
            acc1[k+3].x += w.w*xb.x; acc1[k+3].y += w.w*xb.y;
        }
    }
    __syncthreads();   // all GEMM reads of xs done before overwrite

    // epilogue: x_new = x + gelu(y + tb), write to smem (both tiles) + global
    #pragma unroll
    for (int k = 0; k < 24; k++) {
        int t = tbase + k;
        float bt = tb[t];
        int off = t*Hh + 2*hp;
        float2 o0 = *(float2*)(xs + off);
        o0.x += gelu_exact(acc0[k].x + bt);
        o0.y += gelu_exact(acc0[k].y + bt);
        *(float2*)(xs + off) = o0;
        *(float2*)(xg0 + off) = o0;
        float2 o1 = *(float2*)(xs + SH + off);
        o1.x += gelu_exact(acc1[k].x + bt);
        o1.y += gelu_exact(acc1[k].y + bt);
        *(float2*)(xs + SH + off) = o1;
        *(float2*)(xg1 + off) = o1;
    }
    __syncthreads();

    // phase 2: XW = x_new @ gcn_W   (thread: h = tid&63, grp = tid>>6)
    int h = tid & 63, grp = tid >> 6;
    float wr[Hh];
    #pragma unroll
    for (int k = 0; k < Hh; k++) wr[k] = Wg[k*Hh + h];
    for (int bb = 0; bb < 2; bb++) {
        const float* xsb = xs + bb*SH;
        float* xwo = g_XW + (size_t)(bn0+bb)*SH;
        for (int s = grp; s < Ss; s += 4) {
            const float4* xr = (const float4*)(xsb + s*Hh);
            float acc = 0.f;
            #pragma unroll
            for (int q = 0; q < 16; q++) {
                float4 xv = xr[q];
                acc += xv.x*wr[4*q] + xv.y*wr[4*q+1] + xv.z*wr[4*q+2] + xv.w*wr[4*q+3];
            }
            xwo[s*Hh + h] = acc;
        }
    }
}

// ---------------- kernel: g = A @ XW + gcn_b ; X = LayerNorm(X+g), fused ----------
// block: (24 s-tiles of 8, 5 m-tiles of 40, 32 b). 256 threads: h=tid&63, sc=tid>>6.
// each thread handles 2 s-columns: s = s0 + sc*2 + {0,1}
#define MT 40
__global__ __launch_bounds__(256, 2) void k_mixln(
    const float* __restrict__ gb, const float* __restrict__ lw, const float* __restrict__ lb)
{
    __shared__ float As[Nn*MT];       // [n][m], 32KB
    __shared__ float red[2][8][4];
    int b  = blockIdx.z;
    int m0 = blockIdx.y*MT;
    int s0 = blockIdx.x*8;
    int tid = threadIdx.x;
    int h = tid & 63, sc = tid >> 6;
    int sA = s0 + sc*2;

    // load A rows m0..m0+39 transposed into As[n][m]
    if (tid < Nn) {
        for (int m = 0; m < MT; m++) As[tid*MT + m] = g_A[(m0+m)*Nn + tid];
    }
    __syncthreads();

    float acc0[MT], acc1[MT];
    #pragma unroll
    for (int m = 0; m < MT; m++) { acc0[m] = 0.f; acc1[m] = 0.f; }

    const float* xw = g_XW + ((size_t)b*Nn*Ss + sA)*Hh + h;
    for (int n = 0; n < Nn; n++) {
        float v0 = xw[(size_t)n*SH];
        float v1 = xw[(size_t)n*SH + Hh];
        const float4* a4 = (const float4*)(As + n*MT);
        #pragma unroll
        for (int q = 0; q < 10; q++) {
            float4 a = a4[q];
            acc0[4*q+0] += a.x*v0; acc1[4*q+0] += a.x*v1;
            acc0[4*q+1] += a.y*v0; acc1[4*q+1] += a.y*v1;
            acc0[4*q+2] += a.z*v0; acc1[4*q+2] += a.z*v1;
            acc0[4*q+3] += a.w*v0; acc1[4*q+3] += a.w*v1;
        }
    }

    int lane = tid & 31, w = tid >> 5;
    float gbh = gb[h], lwh = lw[h], lbh = lb[h];
    for (int m = 0; m < MT; m++) {
        int p = m & 1;
        size_t xi = ((size_t)b*Nn + m0 + m)*SH + (size_t)sA*Hh + h;
        float v0 = g_X[xi]      + acc0[m] + gbh;
        float v1 = g_X[xi + Hh] + acc1[m] + gbh;
        float s0v = v0, q0 = v0*v0, s1v = v1, q1 = v1*v1;
        #pragma unroll
        for (int o = 16; o > 0; o >>= 1) {
            s0v += __shfl_down_sync(0xffffffffu, s0v, o);
            q0  += __shfl_down_sync(0xffffffffu, q0,  o);
            s1v += __shfl_down_sync(0xffffffffu, s1v, o);
            q1  += __shfl_down_sync(0xffffffffu, q1,  o);
        }
        if (lane == 0) { red[p][w][0]=s0v; red[p][w][1]=q0; red[p][w][2]=s1v; red[p][w][3]=q1; }
        __syncthreads();
        int wa = w & ~1, wb = w | 1;
        float S0 = red[p][wa][0]+red[p][wb][0], Q0 = red[p][wa][1]+red[p][wb][1];
        float S1 = red[p][wa][2]+red[p][wb][2], Q1 = red[p][wa][3]+red[p][wb][3];
        float mu0 = S0*(1.f/Hh), var0 = Q0*(1.f/Hh) - mu0*mu0;
        float mu1 = S1*(1.f/Hh), var1 = Q1*(1.f/Hh) - mu1*mu1;
        g_X[xi]      = (v0-mu0)*rsqrtf(var0+1e-5f)*lwh + lbh;
        g_X[xi + Hh] = (v1-mu1)*rsqrtf(var1+1e-5f)*lwh + lbh;
    }
}

// ---------------- kernel: future projection ---------------------------------------
__global__ __launch_bounds__(256) void k_futr(
    const float* __restrict__ xf, const float* __restrict__ fw, const float* __restrict__ fb)
{
    int idx = blockIdx.x*blockDim.x + threadIdx.x;
    const int tot = BN*Pp*Hh;
    if (idx >= tot) return;
    int h = idx & 63;
    int p = (idx >> 6) % Pp;
    int bn = idx / (Pp*Hh);
    const float* xr = xf + ((size_t)bn*Pp + p)*FNn;
    float acc = fb[h];
    #pragma unroll
    for (int f = 0; f < FNn; f++) acc += xr[f]*fw[f*Hh+h];
    g_XF[idx] = acc;
}

// ---------------- kernel: head GEMM  out = [X | XF] @ head_W + head_b -------------
__global__ __launch_bounds__(256) void k_head(
    const float* __restrict__ hw, const float* __restrict__ hb, float* __restrict__ out)
{
    __shared__ float Wt[64][48];
    __shared__ float Ft[16][64];
    const int KH = SH;
    const int KT = SH + Pp*Hh;
    int m0 = blockIdx.x*16;
    int tid = threadIdx.x;
    int pcol = tid & 15, mrow = tid >> 4;
    float a0 = 0.f, a1 = 0.f, a2 = 0.f;
    for (int k0 = 0; k0 < KT; k0 += 64) {
        for (int i = tid; i < 64*48; i += 256) {
            int kl = i / 48, p = i % 48;
            Wt[kl][p] = hw[(size_t)(k0+kl)*48 + p];
        }
        for (int i = tid; i < 16*64; i += 256) {
            int ml = i >> 6, kl = i & 63;
            int m = m0 + ml;
            float v;
            if (k0 < KH) v = g_X[(size_t)m*KH + k0 + kl];
            else         v = g_XF[(size_t)m*(Pp*Hh) + (k0 - KH) + kl];
            Ft[ml][kl] = v;
        }
        __syncthreads();
        #pragma unroll 16
        for (int kk = 0; kk < 64; kk++) {
            float fv = Ft[mrow][kk];
            a0 += fv*Wt[kk][pcol];
            a1 += fv*Wt[kk][pcol+16];
            a2 += fv*Wt[kk][pcol+32];
        }
        __syncthreads();
    }
    int m = m0 + mrow;
    out[(size_t)m*Pp + pcol]      = a0 + hb[pcol];
    out[(size_t)m*Pp + pcol + 16] = a1 + hb[pcol+16];
    out[(size_t)m*Pp + pcol + 32] = a2 + hb[pcol+32];
}

// ---------------- launcher ---------------------------------------------------------
extern "C" void kernel_launch(void* const* d_in, const int* in_sizes, int n_in,
                              void* d_out, int out_size)
{
    const float* x        = (const float*)d_in[0];
    const float* x_future = (const float*)d_in[1];
    const float* adj      = (const float*)d_in[2];
    const float* node_emb = (const float*)d_in[3];
    const float* galpha   = (const float*)d_in[4];
    const float* in_w     = (const float*)d_in[5];
    const float* in_b     = (const float*)d_in[6];
    const float* proj_W   = (const float*)d_in[7];
    const float* proj_b   = (const float*)d_in[8];
    const float* temp_W   = (const float*)d_in[9];
    const float* temp_b   = (const float*)d_in[10];
    const float* gcn_W    = (const float*)d_in[11];
    const float* gcn_b    = (const float*)d_in[12];
    const float* ln_w     = (const float*)d_in[13];
    const float* ln_b     = (const float*)d_in[14];
    const float* futr_W   = (const float*)d_in[15];
    const float* futr_b   = (const float*)d_in[16];
    const float* head_W   = (const float*)d_in[17];
    const float* head_b   = (const float*)d_in[18];
    float* out = (float*)d_out;

    static bool attr_set = false;
    if (!attr_set) {
        cudaFuncSetAttribute(k_tempgcn, cudaFuncAttributeMaxDynamicSharedMemorySize, 2*SH*4);
        attr_set = true;
    }

    k_innorm_proj<<<BN, 256>>>(x, in_w, in_b, proj_W, proj_b, node_emb);
    k_adj<<<1, 256>>>(adj, node_emb, galpha);
    for (int i = 0; i < NBb; i++) {
        k_wt<<<dim3(6,6), dim3(32,32)>>>(temp_W + (size_t)i*Ss*Ss);
        k_tempgcn<<<BN/2, 256, 2*SH*4>>>(temp_b + (size_t)i*Ss, gcn_W + (size_t)i*Hh*Hh);
        k_mixln<<<dim3(Ss/8, Nn/MT, Bb), 256>>>(gcn_b + (size_t)i*Hh,
                                                ln_w + (size_t)i*Hh, ln_b + (size_t)i*Hh);
    }
    {
        const int tot = BN*Pp*Hh;
        k_futr<<<(tot + 255)/256, 256>>>(x_future, futr_W, futr_b);
    }
    k_head<<<BN/16, 256>>>(head_W, head_b, out);
}

// round 3
// speedup vs baseline: 1.7358x; 1.3270x over previous
#include <cuda_runtime.h>
#include <math.h>
#include <mma.h>

using namespace nvcuda;

#define Bb 32
#define Nn 200
#define Ss 192
#define Fin 8
#define Hh 64
#define Pp 48
#define FNn 4
#define Kk 10
#define NBb 3
#define BN (Bb*Nn)
#define SH (Ss*Hh)

// scratch (allocation-free rule: __device__ globals)
__device__ float g_X  [BN*SH];
__device__ float g_XW [BN*SH];
__device__ float g_XF [BN*Pp*Hh];
__device__ float g_LA [Nn*Nn];
__device__ float g_LB [Nn*Nn];
__device__ float g_A  [Nn*Nn];
__device__ float g_Atf[256*Nn];   // tf32, rows >=200 zeroed
__device__ float g_D  [Nn];

__device__ __forceinline__ float gelu_exact(float y) {
    return 0.5f*y*(1.f + erff(y*0.70710678118654752f));
}

// ---------------- kernel 1: instance norm + proj + node_emb ------------------------
__global__ __launch_bounds__(256) void k_innorm_proj(
    const float* __restrict__ x, const float* __restrict__ in_w, const float* __restrict__ in_b,
    const float* __restrict__ pw, const float* __restrict__ pb, const float* __restrict__ emb)
{
    __shared__ float xs[Ss*Fin];
    __shared__ float pws[Fin*Hh];
    __shared__ float mu[Fin], ri[Fin];
    int bn = blockIdx.x;
    int tid = threadIdx.x;
    const float* xin = x + (size_t)bn*Ss*Fin;
    for (int i = tid; i < Ss*Fin; i += 256) xs[i] = xin[i];
    for (int i = tid; i < Fin*Hh; i += 256) pws[i] = pw[i];
    __syncthreads();
    if (tid < Fin) {
        float s = 0.f, q = 0.f;
        for (int t = 0; t < Ss; t++) { float v = xs[t*Fin+tid]; s += v; q += v*v; }
        float m = s * (1.f/Ss);
        float var = q * (1.f/Ss) - m*m;
        mu[tid] = m; ri[tid] = rsqrtf(var + 1e-5f);
    }
    __syncthreads();
    for (int i = tid; i < Ss*Fin; i += 256) {
        int f = i & (Fin-1);
        xs[i] = (xs[i]-mu[f])*ri[f]*in_w[f] + in_b[f];
    }
    __syncthreads();
    int h = tid & 63, sb = tid >> 6;
    int n = bn % Nn;
    float bias = pb[h] + emb[n*Hh + h];
    float* xo = g_X + (size_t)bn*SH;
    for (int s = sb; s < Ss; s += 4) {
        float acc = bias;
        #pragma unroll
        for (int f = 0; f < Fin; f++) acc += xs[s*Fin+f]*pws[f*Hh+h];
        xo[s*Hh+h] = acc;
    }
}

// ---------------- kernel 2: learned adjacency + combine + GCN normalization --------
__global__ __launch_bounds__(256) void k_adj(
    const float* __restrict__ adj, const float* __restrict__ emb, const float* __restrict__ ga)
{
    int tid = threadIdx.x;
    for (int e = tid; e < Nn*Nn; e += 256) {
        int i = e / Nn, j = e % Nn;
        float acc = 0.f;
        for (int k = 0; k < Hh; k++) acc += emb[i*Hh+k]*emb[j*Hh+k];
        float v = fmaxf(acc, 0.f);
        g_LA[e] = v; g_LB[e] = v;
    }
    __syncthreads();
    float alpha = ga[0];
    if (tid < Nn) {
        int r = tid;
        const float* la = g_LA + r*Nn;
        float* lb = g_LB + r*Nn;
        int   idxs[Kk];
        float vals[Kk];
        for (int k = 0; k < Kk; k++) {
            float bv = -1e30f; int bi = 0;
            for (int j = 0; j < Nn; j++) { float v = lb[j]; if (v > bv) { bv = v; bi = j; } }
            idxs[k] = bi; vals[k] = la[bi]; lb[bi] = -1e30f;
        }
        float mx = 0.f;
        for (int k = 0; k < Kk; k++) mx = fmaxf(mx, vals[k]);
        float base = expf(0.f - mx);
        float ev[Kk]; float cs = 0.f;
        for (int k = 0; k < Kk; k++) { ev[k] = expf(vals[k]-mx); cs += ev[k]; }
        float inv = 1.f / ((float)(Nn-Kk)*base + cs);
        float* arow = g_A + r*Nn;
        float bsm = base*inv;
        for (int j = 0; j < Nn; j++) arow[j] = bsm;
        for (int k = 0; k < Kk; k++) arow[idxs[k]] = ev[k]*inv;
        float rs = 0.f;
        for (int j = 0; j < Nn; j++) {
            float c = alpha*adj[r*Nn+j] + (1.f-alpha)*arow[j];
            if (j == r) c = 1.f;
            arow[j] = c; rs += c;
        }
        g_D[r] = rsqrtf(fmaxf(rs, 1.f));
    }
    __syncthreads();
    for (int e = tid; e < Nn*Nn; e += 256) {
        int i = e / Nn, j = e % Nn;
        g_A[e] *= g_D[i]*g_D[j];
    }
}

// ---------------- kernel: A (fp32) -> padded tf32 [256][200] -----------------------
__global__ void k_atf()
{
    int idx = blockIdx.x*256 + threadIdx.x;
    if (idx >= 256*Nn) return;
    g_Atf[idx] = (idx < Nn*Nn) ? wmma::__float_to_tf32(g_A[idx]) : 0.f;
}

// ---------------- fused temporal MLP + gcn_W, tensor cores (tf32 wmma) -------------
// one CTA per bn, 256 threads = 8 warps (4 t-blocks x 2 h-blocks)
__global__ __launch_bounds__(256, 2) void k_tempgcn_mma(
    const float* __restrict__ W, const float* __restrict__ tb, const float* __restrict__ Wg)
{
    extern __shared__ float sm[];
    float* Xs  = sm;                    // [192][64]  tf32         48KB
    float* Ws  = Xs + SH;               // 2 x [192][16] tf32      24KB
    float* Wgs = Ws + 2*Ss*16;          // [64][64]  tf32          16KB
    float* Sc  = Wgs + Hh*Hh;           // 8 x [16][16] scratch     8KB
    float* tbs = Sc + 8*256;            // [192]

    int tid = threadIdx.x;
    int wid = tid >> 5, lane = tid & 31;
    int wt = wid >> 1, wh = wid & 1;
    int bn = blockIdx.x;
    float* xg = g_X + (size_t)bn*SH;

    // stage X (RN tf32)
    #pragma unroll
    for (int q = 0; q < 12; q++) {
        int i4 = tid + 256*q;
        float4 v = *(const float4*)(xg + (size_t)i4*4);
        v.x = wmma::__float_to_tf32(v.x); v.y = wmma::__float_to_tf32(v.y);
        v.z = wmma::__float_to_tf32(v.z); v.w = wmma::__float_to_tf32(v.w);
        *(float4*)(Xs + i4*4) = v;
    }
    // stage Wg (RN tf32)
    #pragma unroll
    for (int q = 0; q < 4; q++) {
        int i4 = tid + 256*q;
        float4 v = *(const float4*)(Wg + (size_t)i4*4);
        v.x = wmma::__float_to_tf32(v.x); v.y = wmma::__float_to_tf32(v.y);
        v.z = wmma::__float_to_tf32(v.z); v.w = wmma::__float_to_tf32(v.w);
        *(float4*)(Wgs + i4*4) = v;
    }
    if (tid < Ss) tbs[tid] = tb[tid];

    wmma::fragment<wmma::accumulator,16,16,8,float> c[3][2];
    #pragma unroll
    for (int i = 0; i < 3; i++)
        #pragma unroll
        for (int j = 0; j < 2; j++) wmma::fill_fragment(c[i][j], 0.f);

    // prefetch W chunk 0 into regs
    float4 wreg[3];
    #pragma unroll
    for (int q = 0; q < 3; q++) {
        int i4 = tid + 256*q;
        int row = i4 >> 2, cc = i4 & 3;
        wreg[q] = *(const float4*)(W + (size_t)row*Ss + cc*4);
    }
    __syncthreads();   // Xs/Wgs ready

    // main loop: K = 192 = 12 chunks of 16
    for (int k = 0; k < 12; k++) {
        int p = k & 1;
        float* wbuf = Ws + p*Ss*16;
        #pragma unroll
        for (int q = 0; q < 3; q++) {
            int i4 = tid + 256*q;
            float4 v = wreg[q];
            v.x = wmma::__float_to_tf32(v.x); v.y = wmma::__float_to_tf32(v.y);
            v.z = wmma::__float_to_tf32(v.z); v.w = wmma::__float_to_tf32(v.w);
            *(float4*)(wbuf + i4*4) = v;
        }
        __syncthreads();
        if (k < 11) {
            int s0 = (k+1)*16;
            #pragma unroll
            for (int q = 0; q < 3; q++) {
                int i4 = tid + 256*q;
                int row = i4 >> 2, cc = i4 & 3;
                wreg[q] = *(const float4*)(W + (size_t)row*Ss + s0 + cc*4);
            }
        }
        #pragma unroll
        for (int kk = 0; kk < 2; kk++) {
            wmma::fragment<wmma::matrix_a,16,16,8,wmma::precision::tf32,wmma::row_major> a[3];
            wmma::fragment<wmma::matrix_b,16,16,8,wmma::precision::tf32,wmma::row_major> bf[2];
            #pragma unroll
            for (int i = 0; i < 3; i++)
                wmma::load_matrix_sync(a[i], wbuf + (wt*48 + i*16)*16 + kk*8, 16);
            int srow = k*16 + kk*8;
            #pragma unroll
            for (int j = 0; j < 2; j++)
                wmma::load_matrix_sync(bf[j], Xs + srow*Hh + wh*32 + j*16, Hh);
            #pragma unroll
            for (int i = 0; i < 3; i++)
                #pragma unroll
                for (int j = 0; j < 2; j++)
                    wmma::mma_sync(c[i][j], a[i], bf[j], c[i][j]);
        }
        __syncthreads();
    }

    // epilogue: x_new = x + gelu(y + tb); write g_X (fp32) + Xs (tf32)
    float* scw = Sc + wid*256;
    #pragma unroll
    for (int fm = 0; fm < 3; fm++) {
        #pragma unroll
        for (int fn = 0; fn < 2; fn++) {
            int t0 = wt*48 + fm*16, h0 = wh*32 + fn*16;
            wmma::store_matrix_sync(scw, c[fm][fn], 16, wmma::mem_row_major);
            __syncwarp();
            #pragma unroll
            for (int j = 0; j < 8; j++) {
                int e = lane + 32*j;
                int r = e >> 4, cc = e & 15;
                int t = t0 + r, h = h0 + cc;
                float y = scw[e] + tbs[t];
                float xn = xg[t*Hh + h] + gelu_exact(y);
                xg[t*Hh + h] = xn;
                Xs[t*Hh + h] = wmma::__float_to_tf32(xn);
            }
            __syncwarp();
        }
    }
    __syncthreads();

    // phase 2: XW = x_new @ Wg   (M = s 192, N = 64, K = 64)
    #pragma unroll
    for (int i = 0; i < 3; i++)
        #pragma unroll
        for (int j = 0; j < 2; j++) wmma::fill_fragment(c[i][j], 0.f);
    #pragma unroll
    for (int k8 = 0; k8 < 8; k8++) {
        wmma::fragment<wmma::matrix_a,16,16,8,wmma::precision::tf32,wmma::row_major> a[3];
        wmma::fragment<wmma::matrix_b,16,16,8,wmma::precision::tf32,wmma::row_major> bf[2];
        #pragma unroll
        for (int i = 0; i < 3; i++)
            wmma::load_matrix_sync(a[i], Xs + (wt*48 + i*16)*Hh + k8*8, Hh);
        #pragma unroll
        for (int j = 0; j < 2; j++)
            wmma::load_matrix_sync(bf[j], Wgs + k8*8*Hh + wh*32 + j*16, Hh);
        #pragma unroll
        for (int i = 0; i < 3; i++)
            #pragma unroll
            for (int j = 0; j < 2; j++)
                wmma::mma_sync(c[i][j], a[i], bf[j], c[i][j]);
    }
    float* xwo = g_XW + (size_t)bn*SH;
    #pragma unroll
    for (int i = 0; i < 3; i++)
        #pragma unroll
        for (int j = 0; j < 2; j++)
            wmma::store_matrix_sync(xwo + (wt*48 + i*16)*Hh + wh*32 + j*16,
                                    c[i][j], Hh, wmma::mem_row_major);
}

// ---------------- mixln: g = A @ XW + gb ; X = LN(X+g), tensor cores ---------------
// grid (s-block 192, m-tile 2, b 32); CTA tile 128m x 64sh, K = 200
#define MM 128
__global__ __launch_bounds__(256) void k_mixln_mma(
    const float* __restrict__ gb, const float* __restrict__ lw, const float* __restrict__ lb)
{
    __shared__ float As[2][MM*8];
    __shared__ float Bs[2][8*Hh];
    __shared__ float Out[MM*Hh];
    __shared__ float red[4][2][2];
    int b = blockIdx.z, m0 = blockIdx.y*MM, sblk = blockIdx.x;
    int tid = threadIdx.x, wid = tid >> 5, lane = tid & 31;
    int wm = wid >> 1, whh = wid & 1;

    const float* xwb = g_XW + (size_t)b*Nn*SH + (size_t)sblk*Hh;

    wmma::fragment<wmma::accumulator,16,16,8,float> c[2][2];
    #pragma unroll
    for (int i = 0; i < 2; i++)
        #pragma unroll
        for (int j = 0; j < 2; j++) wmma::fill_fragment(c[i][j], 0.f);

    // prefetch chunk 0
    float4 areg; float4 breg = make_float4(0.f,0.f,0.f,0.f);
    {
        int row = tid >> 1, cc = tid & 1;
        areg = *(const float4*)(g_Atf + (size_t)(m0+row)*Nn + cc*4);
        if (tid < 128) {
            int n = tid >> 4, cb = tid & 15;
            breg = *(const float4*)(xwb + (size_t)n*SH + cb*4);
        }
    }

    for (int k = 0; k < 25; k++) {
        int p = k & 1;
        {
            int row = tid >> 1, cc = tid & 1;
            *(float4*)(&As[p][row*8 + cc*4]) = areg;
            if (tid < 128) {
                int n = tid >> 4, cb = tid & 15;
                float4 v = breg;
                v.x = wmma::__float_to_tf32(v.x); v.y = wmma::__float_to_tf32(v.y);
                v.z = wmma::__float_to_tf32(v.z); v.w = wmma::__float_to_tf32(v.w);
                *(float4*)(&Bs[p][n*Hh + cb*4]) = v;
            }
        }
        __syncthreads();
        if (k < 24) {
            int k0 = (k+1)*8;
            int row = tid >> 1, cc = tid & 1;
            areg = *(const float4*)(g_Atf + (size_t)(m0+row)*Nn + k0 + cc*4);
            if (tid < 128) {
                int n = tid >> 4, cb = tid & 15;
                breg = *(const float4*)(xwb + (size_t)(k0+n)*SH + cb*4);
            }
        }
        wmma::fragment<wmma::matrix_a,16,16,8,wmma::precision::tf32,wmma::row_major> a[2];
        wmma::fragment<wmma::matrix_b,16,16,8,wmma::precision::tf32,wmma::row_major> bf[2];
        #pragma unroll
        for (int i = 0; i < 2; i++)
            wmma::load_matrix_sync(a[i], &As[p][(wm*32 + i*16)*8], 8);
        #pragma unroll
        for (int j = 0; j < 2; j++)
            wmma::load_matrix_sync(bf[j], &Bs[p][whh*32 + j*16], Hh);
        #pragma unroll
        for (int i = 0; i < 2; i++)
            #pragma unroll
            for (int j = 0; j < 2; j++)
                wmma::mma_sync(c[i][j], a[i], bf[j], c[i][j]);
        __syncthreads();
    }

    #pragma unroll
    for (int i = 0; i < 2; i++)
        #pragma unroll
        for (int j = 0; j < 2; j++)
            wmma::store_matrix_sync(Out + (wm*32 + i*16)*Hh + whh*32 + j*16,
                                    c[i][j], Hh, wmma::mem_row_major);
    __syncthreads();

    // residual + LayerNorm per row
    int h = tid & 63, rg = tid >> 6;
    float gbh = gb[h], lwh = lw[h], lbh = lb[h];
    for (int it = 0; it < 32; it++) {
        int r = it*4 + rg;
        int m = m0 + r;
        bool valid = (m < Nn);
        size_t xi = ((size_t)(b*Nn + m)*Ss + sblk)*Hh + h;
        float v = 0.f;
        if (valid) v = g_X[xi] + Out[r*Hh + h] + gbh;
        float s = v, q = v*v;
        #pragma unroll
        for (int o = 16; o > 0; o >>= 1) {
            s += __shfl_down_sync(0xffffffffu, s, o);
            q += __shfl_down_sync(0xffffffffu, q, o);
        }
        if (lane == 0) { red[rg][wid & 1][0] = s; red[rg][wid & 1][1] = q; }
        __syncthreads();
        float S = red[rg][0][0] + red[rg][1][0];
        float Q = red[rg][0][1] + red[rg][1][1];
        float mu = S*(1.f/Hh), var = Q*(1.f/Hh) - mu*mu;
        if (valid) g_X[xi] = (v-mu)*rsqrtf(var+1e-5f)*lwh + lbh;
        __syncthreads();
    }
}

// ---------------- kernel: future projection ---------------------------------------
__global__ __launch_bounds__(256) void k_futr(
    const float* __restrict__ xf, const float* __restrict__ fw, const float* __restrict__ fb)
{
    int idx = blockIdx.x*blockDim.x + threadIdx.x;
    const int tot = BN*Pp*Hh;
    if (idx >= tot) return;
    int h = idx & 63;
    int p = (idx >> 6) % Pp;
    int bn = idx / (Pp*Hh);
    const float* xr = xf + ((size_t)bn*Pp + p)*FNn;
    float acc = fb[h];
    #pragma unroll
    for (int f = 0; f < FNn; f++) acc += xr[f]*fw[f*Hh+h];
    g_XF[idx] = acc;
}

// ---------------- kernel: head GEMM  out = [X | XF] @ head_W + head_b -------------
__global__ __launch_bounds__(256) void k_head(
    const float* __restrict__ hw, const float* __restrict__ hb, float* __restrict__ out)
{
    __shared__ float Wt[64][48];
    __shared__ float Ft[16][64];
    const int KH = SH;
    const int KT = SH + Pp*Hh;
    int m0 = blockIdx.x*16;
    int tid = threadIdx.x;
    int pcol = tid & 15, mrow = tid >> 4;
    float a0 = 0.f, a1 = 0.f, a2 = 0.f;
    for (int k0 = 0; k0 < KT; k0 += 64) {
        for (int i = tid; i < 64*48; i += 256) {
            int kl = i / 48, p = i % 48;
            Wt[kl][p] = hw[(size_t)(k0+kl)*48 + p];
        }
        for (int i = tid; i < 16*64; i += 256) {
            int ml = i >> 6, kl = i & 63;
            int m = m0 + ml;
            float v;
            if (k0 < KH) v = g_X[(size_t)m*KH + k0 + kl];
            else         v = g_XF[(size_t)m*(Pp*Hh) + (k0 - KH) + kl];
            Ft[ml][kl] = v;
        }
        __syncthreads();
        #pragma unroll 16
        for (int kk = 0; kk < 64; kk++) {
            float fv = Ft[mrow][kk];
            a0 += fv*Wt[kk][pcol];
            a1 += fv*Wt[kk][pcol+16];
            a2 += fv*Wt[kk][pcol+32];
        }
        __syncthreads();
    }
    int m = m0 + mrow;
    out[(size_t)m*Pp + pcol]      = a0 + hb[pcol];
    out[(size_t)m*Pp + pcol + 16] = a1 + hb[pcol+16];
    out[(size_t)m*Pp + pcol + 32] = a2 + hb[pcol+32];
}

// ---------------- launcher ---------------------------------------------------------
#define TEMPGCN_SMEM ((SH + 2*Ss*16 + Hh*Hh + 8*256 + Ss)*4)

extern "C" void kernel_launch(void* const* d_in, const int* in_sizes, int n_in,
                              void* d_out, int out_size)
{
    const float* x        = (const float*)d_in[0];
    const float* x_future = (const float*)d_in[1];
    const float* adj      = (const float*)d_in[2];
    const float* node_emb = (const float*)d_in[3];
    const float* galpha   = (const float*)d_in[4];
    const float* in_w     = (const float*)d_in[5];
    const float* in_b     = (const float*)d_in[6];
    const float* proj_W   = (const float*)d_in[7];
    const float* proj_b   = (const float*)d_in[8];
    const float* temp_W   = (const float*)d_in[9];
    const float* temp_b   = (const float*)d_in[10];
    const float* gcn_W    = (const float*)d_in[11];
    const float* gcn_b    = (const float*)d_in[12];
    const float* ln_w     = (const float*)d_in[13];
    const float* ln_b     = (const float*)d_in[14];
    const float* futr_W   = (const float*)d_in[15];
    const float* futr_b   = (const float*)d_in[16];
    const float* head_W   = (const float*)d_in[17];
    const float* head_b   = (const float*)d_in[18];
    float* out = (float*)d_out;

    static bool attr_set = false;
    if (!attr_set) {
        cudaFuncSetAttribute(k_tempgcn_mma, cudaFuncAttributeMaxDynamicSharedMemorySize, TEMPGCN_SMEM);
        attr_set = true;
    }

    k_innorm_proj<<<BN, 256>>>(x, in_w, in_b, proj_W, proj_b, node_emb);
    k_adj<<<1, 256>>>(adj, node_emb, galpha);
    k_atf<<<(256*Nn + 255)/256, 256>>>();
    for (int i = 0; i < NBb; i++) {
        k_tempgcn_mma<<<BN, 256, TEMPGCN_SMEM>>>(temp_W + (size_t)i*Ss*Ss,
                                                 temp_b + (size_t)i*Ss,
                                                 gcn_W + (size_t)i*Hh*Hh);
        k_mixln_mma<<<dim3(Ss, 2, Bb), 256>>>(gcn_b + (size_t)i*Hh,
                                              ln_w + (size_t)i*Hh, ln_b + (size_t)i*Hh);
    }
    {
        const int tot = BN*Pp*Hh;
        k_futr<<<(tot + 255)/256, 256>>>(x_future, futr_W, futr_b);
    }
    k_head<<<BN/16, 256>>>(head_W, head_b, out);
}

// round 4
// speedup vs baseline: 1.9925x; 1.1479x over previous
#include <cuda_runtime.h>
#include <math.h>
#include <mma.h>

using namespace nvcuda;

#define Bb 32
#define Nn 200
#define Ss 192
#define Fin 8
#define Hh 64
#define Pp 48
#define FNn 4
#define Kk 10
#define NBb 3
#define BN (Bb*Nn)
#define SH (Ss*Hh)

#define XP 68   // padded ldm for 64-wide tiles
#define WP 20   // padded ldm for 16-wide W chunks
#define AP 44   // padded ldm for 40-wide A chunks

// scratch (allocation-free rule: __device__ globals)
__device__ float g_X  [BN*SH];
__device__ float g_XW [BN*SH];
__device__ float g_XF [BN*Pp*Hh];
__device__ float g_LA [Nn*Nn];
__device__ float g_LB [Nn*Nn];
__device__ float g_A  [Nn*Nn];
__device__ float g_Atf[256*Nn];   // tf32, rows >=200 zeroed
__device__ float g_D  [Nn];

__device__ __forceinline__ float gelu_exact(float y) {
    return 0.5f*y*(1.f + erff(y*0.70710678118654752f));
}

// ---------------- kernel 1: instance norm + proj + node_emb ------------------------
__global__ __launch_bounds__(256) void k_innorm_proj(
    const float* __restrict__ x, const float* __restrict__ in_w, const float* __restrict__ in_b,
    const float* __restrict__ pw, const float* __restrict__ pb, const float* __restrict__ emb)
{
    __shared__ float xs[Ss*Fin];
    __shared__ float pws[Fin*Hh];
    __shared__ float mu[Fin], ri[Fin];
    int bn = blockIdx.x;
    int tid = threadIdx.x;
    const float* xin = x + (size_t)bn*Ss*Fin;
    for (int i = tid; i < Ss*Fin; i += 256) xs[i] = xin[i];
    for (int i = tid; i < Fin*Hh; i += 256) pws[i] = pw[i];
    __syncthreads();
    if (tid < Fin) {
        float s = 0.f, q = 0.f;
        for (int t = 0; t < Ss; t++) { float v = xs[t*Fin+tid]; s += v; q += v*v; }
        float m = s * (1.f/Ss);
        float var = q * (1.f/Ss) - m*m;
        mu[tid] = m; ri[tid] = rsqrtf(var + 1e-5f);
    }
    __syncthreads();
    for (int i = tid; i < Ss*Fin; i += 256) {
        int f = i & (Fin-1);
        xs[i] = (xs[i]-mu[f])*ri[f]*in_w[f] + in_b[f];
    }
    __syncthreads();
    int h = tid & 63, sb = tid >> 6;
    int n = bn % Nn;
    float bias = pb[h] + emb[n*Hh + h];
    float* xo = g_X + (size_t)bn*SH;
    for (int s = sb; s < Ss; s += 4) {
        float acc = bias;
        #pragma unroll
        for (int f = 0; f < Fin; f++) acc += xs[s*Fin+f]*pws[f*Hh+h];
        xo[s*Hh+h] = acc;
    }
}

// ---------------- kernel 2: learned adjacency + combine + GCN normalization --------
__global__ __launch_bounds__(256) void k_adj(
    const float* __restrict__ adj, const float* __restrict__ emb, const float* __restrict__ ga)
{
    int tid = threadIdx.x;
    for (int e = tid; e < Nn*Nn; e += 256) {
        int i = e / Nn, j = e % Nn;
        float acc = 0.f;
        for (int k = 0; k < Hh; k++) acc += emb[i*Hh+k]*emb[j*Hh+k];
        float v = fmaxf(acc, 0.f);
        g_LA[e] = v; g_LB[e] = v;
    }
    __syncthreads();
    float alpha = ga[0];
    if (tid < Nn) {
        int r = tid;
        const float* la = g_LA + r*Nn;
        float* lb = g_LB + r*Nn;
        int   idxs[Kk];
        float vals[Kk];
        for (int k = 0; k < Kk; k++) {
            float bv = -1e30f; int bi = 0;
            for (int j = 0; j < Nn; j++) { float v = lb[j]; if (v > bv) { bv = v; bi = j; } }
            idxs[k] = bi; vals[k] = la[bi]; lb[bi] = -1e30f;
        }
        float mx = 0.f;
        for (int k = 0; k < Kk; k++) mx = fmaxf(mx, vals[k]);
        float base = expf(0.f - mx);
        float ev[Kk]; float cs = 0.f;
        for (int k = 0; k < Kk; k++) { ev[k] = expf(vals[k]-mx); cs += ev[k]; }
        float inv = 1.f / ((float)(Nn-Kk)*base + cs);
        float* arow = g_A + r*Nn;
        float bsm = base*inv;
        for (int j = 0; j < Nn; j++) arow[j] = bsm;
        for (int k = 0; k < Kk; k++) arow[idxs[k]] = ev[k]*inv;
        float rs = 0.f;
        for (int j = 0; j < Nn; j++) {
            float c = alpha*adj[r*Nn+j] + (1.f-alpha)*arow[j];
            if (j == r) c = 1.f;
            arow[j] = c; rs += c;
        }
        g_D[r] = rsqrtf(fmaxf(rs, 1.f));
    }
    __syncthreads();
    for (int e = tid; e < Nn*Nn; e += 256) {
        int i = e / Nn, j = e % Nn;
        g_A[e] *= g_D[i]*g_D[j];
    }
}

// ---------------- kernel: A (fp32) -> padded tf32 [256][200] -----------------------
__global__ void k_atf()
{
    int idx = blockIdx.x*256 + threadIdx.x;
    if (idx >= 256*Nn) return;
    g_Atf[idx] = (idx < Nn*Nn) ? wmma::__float_to_tf32(g_A[idx]) : 0.f;
}

// ---------------- fused temporal MLP + gcn_W, tf32 wmma, padded smem ---------------
// one CTA per bn; 8 warps: wt = wid>>1 (48 t-rows each), wh = wid&1 (32 h each)
#define TG_SMEM ((Ss*XP + 2*Ss*WP + Hh*XP + Ss)*4)
__global__ __launch_bounds__(256) void k_tempgcn_mma(
    const float* __restrict__ W, const float* __restrict__ tb, const float* __restrict__ Wg)
{
    extern __shared__ float sm[];
    float* Xs  = sm;                    // [192][XP]
    float* Ws  = Xs + Ss*XP;            // 2 x [192][WP]
    float* Wgs = Ws + 2*Ss*WP;          // [64][XP]
    float* tbs = Wgs + Hh*XP;           // [192]

    int tid = threadIdx.x;
    int wid = tid >> 5;
    int wt = wid >> 1, wh = wid & 1;
    int bn = blockIdx.x;
    float* xg = g_X + (size_t)bn*SH;

    // stage X (tf32, padded)
    #pragma unroll
    for (int q = 0; q < 12; q++) {
        int i4 = tid + 256*q;
        int t = i4 >> 4, c4 = i4 & 15;
        float4 v = *(const float4*)(xg + (size_t)t*Hh + c4*4);
        v.x = wmma::__float_to_tf32(v.x); v.y = wmma::__float_to_tf32(v.y);
        v.z = wmma::__float_to_tf32(v.z); v.w = wmma::__float_to_tf32(v.w);
        *(float4*)(Xs + t*XP + c4*4) = v;
    }
    // stage Wg (tf32, padded)
    #pragma unroll
    for (int q = 0; q < 4; q++) {
        int i4 = tid + 256*q;
        int r = i4 >> 4, c4 = i4 & 15;
        float4 v = *(const float4*)(Wg + (size_t)r*Hh + c4*4);
        v.x = wmma::__float_to_tf32(v.x); v.y = wmma::__float_to_tf32(v.y);
        v.z = wmma::__float_to_tf32(v.z); v.w = wmma::__float_to_tf32(v.w);
        *(float4*)(Wgs + r*XP + c4*4) = v;
    }
    if (tid < Ss) tbs[tid] = tb[tid];

    wmma::fragment<wmma::accumulator,16,16,8,float> c[3][2];
    #pragma unroll
    for (int i = 0; i < 3; i++)
        #pragma unroll
        for (int j = 0; j < 2; j++) wmma::fill_fragment(c[i][j], 0.f);

    // prefetch W chunk 0
    float4 wreg[3];
    #pragma unroll
    for (int q = 0; q < 3; q++) {
        int i4 = tid + 256*q;
        int row = i4 >> 2, cc = i4 & 3;
        wreg[q] = *(const float4*)(W + (size_t)row*Ss + cc*4);
    }
    __syncthreads();

    for (int k = 0; k < 12; k++) {
        float* wbuf = Ws + (k & 1)*Ss*WP;
        #pragma unroll
        for (int q = 0; q < 3; q++) {
            int i4 = tid + 256*q;
            int row = i4 >> 2, cc = i4 & 3;
            float4 v = wreg[q];
            v.x = wmma::__float_to_tf32(v.x); v.y = wmma::__float_to_tf32(v.y);
            v.z = wmma::__float_to_tf32(v.z); v.w = wmma::__float_to_tf32(v.w);
            *(float4*)(wbuf + row*WP + cc*4) = v;
        }
        __syncthreads();
        if (k < 11) {
            int s0 = (k+1)*16;
            #pragma unroll
            for (int q = 0; q < 3; q++) {
                int i4 = tid + 256*q;
                int row = i4 >> 2, cc = i4 & 3;
                wreg[q] = *(const float4*)(W + (size_t)row*Ss + s0 + cc*4);
            }
        }
        #pragma unroll
        for (int kk = 0; kk < 2; kk++) {
            wmma::fragment<wmma::matrix_a,16,16,8,wmma::precision::tf32,wmma::row_major> a[3];
            wmma::fragment<wmma::matrix_b,16,16,8,wmma::precision::tf32,wmma::row_major> bf[2];
            #pragma unroll
            for (int i = 0; i < 3; i++)
                wmma::load_matrix_sync(a[i], wbuf + (wt*48 + i*16)*WP + kk*8, WP);
            int srow = k*16 + kk*8;
            #pragma unroll
            for (int j = 0; j < 2; j++)
                wmma::load_matrix_sync(bf[j], Xs + srow*XP + wh*32 + j*16, XP);
            #pragma unroll
            for (int i = 0; i < 3; i++)
                #pragma unroll
                for (int j = 0; j < 2; j++)
                    wmma::mma_sync(c[i][j], a[i], bf[j], c[i][j]);
        }
        __syncthreads();
    }

    // store Y directly into Xs (x tile dead after final sync)
    #pragma unroll
    for (int i = 0; i < 3; i++)
        #pragma unroll
        for (int j = 0; j < 2; j++)
            wmma::store_matrix_sync(Xs + (wt*48 + i*16)*XP + wh*32 + j*16,
                                    c[i][j], XP, wmma::mem_row_major);
    __syncthreads();

    // elementwise: xn = x + gelu(y + tb); write g_X fp32 + Xs tf32
    #pragma unroll
    for (int q = 0; q < 48; q++) {
        int i = tid + 256*q;
        int t = i >> 6, h = i & 63;
        float y = Xs[t*XP + h] + tbs[t];
        float xn = xg[i] + gelu_exact(y);
        xg[i] = xn;
        Xs[t*XP + h] = wmma::__float_to_tf32(xn);
    }
    __syncthreads();

    // phase 2: XW = x_new @ Wg
    #pragma unroll
    for (int i = 0; i < 3; i++)
        #pragma unroll
        for (int j = 0; j < 2; j++) wmma::fill_fragment(c[i][j], 0.f);
    #pragma unroll
    for (int k8 = 0; k8 < 8; k8++) {
        wmma::fragment<wmma::matrix_a,16,16,8,wmma::precision::tf32,wmma::row_major> a[3];
        wmma::fragment<wmma::matrix_b,16,16,8,wmma::precision::tf32,wmma::row_major> bf[2];
        #pragma unroll
        for (int i = 0; i < 3; i++)
            wmma::load_matrix_sync(a[i], Xs + (wt*48 + i*16)*XP + k8*8, XP);
        #pragma unroll
        for (int j = 0; j < 2; j++)
            wmma::load_matrix_sync(bf[j], Wgs + k8*8*XP + wh*32 + j*16, XP);
        #pragma unroll
        for (int i = 0; i < 3; i++)
            #pragma unroll
            for (int j = 0; j < 2; j++)
                wmma::mma_sync(c[i][j], a[i], bf[j], c[i][j]);
    }
    float* xwo = g_XW + (size_t)bn*SH;
    #pragma unroll
    for (int i = 0; i < 3; i++)
        #pragma unroll
        for (int j = 0; j < 2; j++)
            wmma::store_matrix_sync(xwo + (wt*48 + i*16)*Hh + wh*32 + j*16,
                                    c[i][j], Hh, wmma::mem_row_major);
}

// ---------------- mixln: g = A @ XW + gb ; X = LN(X+g) -----------------------------
// grid (Ss, 2, Bb); CTA tile 128m x 64sh; K = 200 in 5 chunks of 40; warp-local LN
#define MM 128
#define KC 40
#define ML_SMEM ((MM*AP + KC*XP + MM*XP)*4)
__global__ __launch_bounds__(256, 3) void k_mixln_mma(
    const float* __restrict__ gb, const float* __restrict__ lw, const float* __restrict__ lb)
{
    extern __shared__ float sm[];
    float* As  = sm;                  // [128][AP]
    float* Bs  = As + MM*AP;          // [40][XP]
    float* Out = Bs + KC*XP;          // [128][XP]

    int b = blockIdx.z, m0 = blockIdx.y*MM, sblk = blockIdx.x;
    int tid = threadIdx.x, wid = tid >> 5, lane = tid & 31;
    int wm = wid >> 1, whh = wid & 1;

    const float* xwb = g_XW + (size_t)b*Nn*SH + (size_t)sblk*Hh;

    wmma::fragment<wmma::accumulator,16,16,8,float> c[2][2];
    #pragma unroll
    for (int i = 0; i < 2; i++)
        #pragma unroll
        for (int j = 0; j < 2; j++) wmma::fill_fragment(c[i][j], 0.f);

    for (int kc = 0; kc < 5; kc++) {
        int k0 = kc*KC;
        // stage A chunk [128][40] (already tf32)
        #pragma unroll
        for (int q = 0; q < 5; q++) {
            int i4 = tid + 256*q;
            int row = i4 / 10, c4 = i4 % 10;
            *(float4*)(As + row*AP + c4*4) =
                *(const float4*)(g_Atf + (size_t)(m0+row)*Nn + k0 + c4*4);
        }
        // stage B chunk [40][64] tf32
        for (int i4 = tid; i4 < KC*16; i4 += 256) {
            int n = i4 >> 4, c4 = i4 & 15;
            float4 v = *(const float4*)(xwb + (size_t)(k0+n)*SH + c4*4);
            v.x = wmma::__float_to_tf32(v.x); v.y = wmma::__float_to_tf32(v.y);
            v.z = wmma::__float_to_tf32(v.z); v.w = wmma::__float_to_tf32(v.w);
            *(float4*)(Bs + n*XP + c4*4) = v;
        }
        __syncthreads();
        #pragma unroll
        for (int kk = 0; kk < 5; kk++) {
            wmma::fragment<wmma::matrix_a,16,16,8,wmma::precision::tf32,wmma::row_major> a[2];
            wmma::fragment<wmma::matrix_b,16,16,8,wmma::precision::tf32,wmma::row_major> bf[2];
            #pragma unroll
            for (int i = 0; i < 2; i++)
                wmma::load_matrix_sync(a[i], As + (wm*32 + i*16)*AP + kk*8, AP);
            #pragma unroll
            for (int j = 0; j < 2; j++)
                wmma::load_matrix_sync(bf[j], Bs + kk*8*XP + whh*32 + j*16, XP);
            #pragma unroll
            for (int i = 0; i < 2; i++)
                #pragma unroll
                for (int j = 0; j < 2; j++)
                    wmma::mma_sync(c[i][j], a[i], bf[j], c[i][j]);
        }
        __syncthreads();
    }

    #pragma unroll
    for (int i = 0; i < 2; i++)
        #pragma unroll
        for (int j = 0; j < 2; j++)
            wmma::store_matrix_sync(Out + (wm*32 + i*16)*XP + whh*32 + j*16,
                                    c[i][j], XP, wmma::mem_row_major);
    __syncthreads();

    // warp-local residual + LayerNorm: each warp owns 16 complete rows
    float gb0 = gb[lane],    gb1 = gb[lane+32];
    float lw0 = lw[lane],    lw1 = lw[lane+32];
    float lb0 = lb[lane],    lb1 = lb[lane+32];
    #pragma unroll
    for (int it = 0; it < 16; it++) {
        int r = wid*16 + it;
        int m = m0 + r;
        if (m >= Nn) break;
        size_t xi = ((size_t)(b*Nn + m)*Ss + sblk)*Hh + lane;
        float v0 = g_X[xi]      + Out[r*XP + lane]      + gb0;
        float v1 = g_X[xi + 32] + Out[r*XP + lane + 32] + gb1;
        float s = v0 + v1, q = v0*v0 + v1*v1;
        #pragma unroll
        for (int o = 16; o > 0; o >>= 1) {
            s += __shfl_xor_sync(0xffffffffu, s, o);
            q += __shfl_xor_sync(0xffffffffu, q, o);
        }
        float mu = s*(1.f/Hh), var = q*(1.f/Hh) - mu*mu;
        float rinv = rsqrtf(var + 1e-5f);
        g_X[xi]      = (v0-mu)*rinv*lw0 + lb0;
        g_X[xi + 32] = (v1-mu)*rinv*lw1 + lb1;
    }
}

// ---------------- kernel: future projection ---------------------------------------
__global__ __launch_bounds__(256) void k_futr(
    const float* __restrict__ xf, const float* __restrict__ fw, const float* __restrict__ fb)
{
    int idx = blockIdx.x*blockDim.x + threadIdx.x;
    const int tot = BN*Pp*Hh;
    if (idx >= tot) return;
    int h = idx & 63;
    int p = (idx >> 6) % Pp;
    int bn = idx / (Pp*Hh);
    const float* xr = xf + ((size_t)bn*Pp + p)*FNn;
    float acc = fb[h];
    #pragma unroll
    for (int f = 0; f < FNn; f++) acc += xr[f]*fw[f*Hh+h];
    g_XF[idx] = acc;
}

// ---------------- kernel: head GEMM  out = [X | XF] @ head_W + head_b -------------
__global__ __launch_bounds__(256) void k_head(
    const float* __restrict__ hw, const float* __restrict__ hb, float* __restrict__ out)
{
    __shared__ float Wt[64][48];
    __shared__ float Ft[16][64];
    const int KH = SH;
    const int KT = SH + Pp*Hh;
    int m0 = blockIdx.x*16;
    int tid = threadIdx.x;
    int pcol = tid & 15, mrow = tid >> 4;
    float a0 = 0.f, a1 = 0.f, a2 = 0.f;
    for (int k0 = 0; k0 < KT; k0 += 64) {
        for (int i = tid; i < 64*48; i += 256) {
            int kl = i / 48, p = i % 48;
            Wt[kl][p] = hw[(size_t)(k0+kl)*48 + p];
        }
        for (int i = tid; i < 16*64; i += 256) {
            int ml = i >> 6, kl = i & 63;
            int m = m0 + ml;
            float v;
            if (k0 < KH) v = g_X[(size_t)m*KH + k0 + kl];
            else         v = g_XF[(size_t)m*(Pp*Hh) + (k0 - KH) + kl];
            Ft[ml][kl] = v;
        }
        __syncthreads();
        #pragma unroll 16
        for (int kk = 0; kk < 64; kk++) {
            float fv = Ft[mrow][kk];
            a0 += fv*Wt[kk][pcol];
            a1 += fv*Wt[kk][pcol+16];
            a2 += fv*Wt[kk][pcol+32];
        }
        __syncthreads();
    }
    int m = m0 + mrow;
    out[(size_t)m*Pp + pcol]      = a0 + hb[pcol];
    out[(size_t)m*Pp + pcol + 16] = a1 + hb[pcol+16];
    out[(size_t)m*Pp + pcol + 32] = a2 + hb[pcol+32];
}

// ---------------- launcher ---------------------------------------------------------
extern "C" void kernel_launch(void* const* d_in, const int* in_sizes, int n_in,
                              void* d_out, int out_size)
{
    const float* x        = (const float*)d_in[0];
    const float* x_future = (const float*)d_in[1];
    const float* adj      = (const float*)d_in[2];
    const float* node_emb = (const float*)d_in[3];
    const float* galpha   = (const float*)d_in[4];
    const float* in_w     = (const float*)d_in[5];
    const float* in_b     = (const float*)d_in[6];
    const float* proj_W   = (const float*)d_in[7];
    const float* proj_b   = (const float*)d_in[8];
    const float* temp_W   = (const float*)d_in[9];
    const float* temp_b   = (const float*)d_in[10];
    const float* gcn_W    = (const float*)d_in[11];
    const float* gcn_b    = (const float*)d_in[12];
    const float* ln_w     = (const float*)d_in[13];
    const float* ln_b     = (const float*)d_in[14];
    const float* futr_W   = (const float*)d_in[15];
    const float* futr_b   = (const float*)d_in[16];
    const float* head_W   = (const float*)d_in[17];
    const float* head_b   = (const float*)d_in[18];
    float* out = (float*)d_out;

    static bool attr_set = false;
    if (!attr_set) {
        cudaFuncSetAttribute(k_tempgcn_mma, cudaFuncAttributeMaxDynamicSharedMemorySize, TG_SMEM);
        cudaFuncSetAttribute(k_mixln_mma,   cudaFuncAttributeMaxDynamicSharedMemorySize, ML_SMEM);
        attr_set = true;
    }

    k_innorm_proj<<<BN, 256>>>(x, in_w, in_b, proj_W, proj_b, node_emb);
    k_adj<<<1, 256>>>(adj, node_emb, galpha);
    k_atf<<<(256*Nn + 255)/256, 256>>>();
    for (int i = 0; i < NBb; i++) {
        k_tempgcn_mma<<<BN, 256, TG_SMEM>>>(temp_W + (size_t)i*Ss*Ss,
                                            temp_b + (size_t)i*Ss,
                                            gcn_W + (size_t)i*Hh*Hh);
        k_mixln_mma<<<dim3(Ss, 2, Bb), 256, ML_SMEM>>>(gcn_b + (size_t)i*Hh,
                                                       ln_w + (size_t)i*Hh, ln_b + (size_t)i*Hh);
    }
    {
        const int tot = BN*Pp*Hh;
        k_futr<<<(tot + 255)/256, 256>>>(x_future, futr_W, futr_b);
    }
    k_head<<<BN/16, 256>>>(head_W, head_b, out);
}